// round 4
// baseline (speedup 1.0000x reference)
#include <cuda_runtime.h>
#include <math.h>

#define BSZ 8192
#define KC 10
#define NC 100
#define LAMBDA 1.0f
#define WPB 8
#define REC 160   // per-batch record: Q[0..54], pad, D[56..145], yw[146..148]

__device__ float d_wsum;
__device__ float d_sw[NC];
__device__ float d_Bb[NC * 30];   // [n][a][k]
__device__ float d_G[KC * KC];
__device__ float d_g[KC];
__device__ float d_bw[KC * 3];    // [k][a]
__device__ float d_q00;
__device__ float gRec[BSZ * REC];

// ---------------- setup ----------------
__global__ void setup_kernel(const float* __restrict__ w, const float* __restrict__ mk)
{
    __shared__ float s_red[128];
    __shared__ float s_bw[30];
    __shared__ float sS[100];
    __shared__ float sHinv[100];
    __shared__ float sM[10][20];
    __shared__ float s_wsum, s_denom;
    __shared__ float sHt[10];

    int t = threadIdx.x;
    float acc = 0.f;
    for (int n = t; n < NC; n += 128) acc += w[n];
    s_red[t] = acc; __syncthreads();
    for (int off = 64; off > 0; off >>= 1) { if (t < off) s_red[t] += s_red[t + off]; __syncthreads(); }
    if (t == 0) { s_wsum = s_red[0]; d_wsum = s_red[0]; }
    __syncthreads();
    float wsum = s_wsum;
    if (t < NC) d_sw[t] = sqrtf(w[t]);
    if (t < 30) {
        int k = t / 3, a = t % 3;
        float s = 0.f;
        for (int n = 0; n < NC; n++) s += mk[k * 300 + a * 100 + n] * w[n];
        s_bw[t] = s / wsum; d_bw[t] = s / wsum;
    }
    __syncthreads();
    for (int i = t; i < NC * 30; i += 128) {
        int n = i / 30, rem = i % 30, a = rem / 10, k = rem % 10;
        d_Bb[i] = sqrtf(w[n]) * (mk[k * 300 + a * 100 + n] - s_bw[k * 3 + a]);
    }
    __syncthreads();
    if (t < 55) {
        int k = 0, uu = t;
        while (uu >= KC - k) { uu -= KC - k; k++; }
        int k2 = k + uu;
        float s = 0.f;
        for (int n = 0; n < NC; n++)
            for (int p = 0; p < 3; p++) {
                int base = n * 30 + p * 10;
                s += d_Bb[base + k] * d_Bb[base + k2];
            }
        sS[k * 10 + k2] = s; sS[k2 * 10 + k] = s;
    }
    __syncthreads();
    if (t < 100) {
        int i = t / 10, j = t % 10;
        sM[i][j] = 2.f * (sS[t] + ((i == j) ? LAMBDA : 0.f));
        sM[i][10 + j] = (i == j) ? 1.f : 0.f;
    }
    __syncthreads();
    for (int piv = 0; piv < 10; piv++) {
        if (t == 0) {
            float inv = 1.f / sM[piv][piv];
            for (int j = 0; j < 20; j++) sM[piv][j] *= inv;
        }
        __syncthreads();
        if (t < 10 && t != piv) {
            float f = sM[t][piv];
            for (int j = 0; j < 20; j++) sM[t][j] -= f * sM[piv][j];
        }
        __syncthreads();
    }
    if (t < 100) sHinv[t] = sM[t / 10][10 + (t % 10)];
    __syncthreads();
    if (t < 10) {
        float s = 0.f;
        for (int j = 0; j < 10; j++) s += sHinv[t * 10 + j];
        sHt[t] = s;
    }
    __syncthreads();
    if (t == 0) {
        float d = 0.f;
        for (int i = 0; i < 10; i++) d += sHt[i];
        s_denom = d;
    }
    __syncthreads();
    float denom = s_denom;
    if (t < 100) d_G[t] = sHinv[t] - sHt[t / 10] * sHt[t % 10] / denom;
    if (t < 10) d_g[t] = sHt[t] / denom;
    if (t == 0) {
        float q = 0.f;
        for (int i = 0; i < 10; i++) {
            float gi = sHt[i] / denom;
            float sg = 0.f;
            for (int j = 0; j < 10; j++) sg += sS[i * 10 + j] * sHt[j] / denom;
            q += gi * sg + LAMBDA * gi * gi;
        }
        d_q00 = q;
    }
}

// ---------------- phase A: warp per batch ----------------
__global__ __launch_bounds__(256) void phaseA_kernel(const float* __restrict__ y,
                                                     const float* __restrict__ w)
{
    __shared__ float sBb[3000];
    __shared__ float sG[100];
    __shared__ float sg[12];
    __shared__ float swt[100];
    __shared__ float ssw[100];
    __shared__ float4 sY4[WPB][101];
    __shared__ float sD[WPB][92];
    __shared__ float sT[WPB][92];
    __shared__ float sYY[WPB][12];
    __shared__ float sq00, sinvw;

    int tid = threadIdx.x;
    for (int i = tid; i < 3000; i += 256) sBb[i] = d_Bb[i];
    if (tid < 100) { sG[tid] = d_G[tid]; swt[tid] = w[tid]; ssw[tid] = d_sw[tid]; }
    if (tid < 10) sg[tid] = d_g[tid];
    if (tid == 0) { sq00 = d_q00; sinvw = 1.f / d_wsum; }
    __syncthreads();

    int wid = tid / 32, lane = tid % 32;
    int b = blockIdx.x * WPB + wid;
    const float* yb = y + b * 300;
    float* sYf = (float*)&sY4[wid][0];

    for (int i = lane; i < 300; i += 32) {
        int r = i / 100, n = i % 100;
        sYf[n * 4 + r] = yb[i];
    }
    __syncwarp();

    float p0 = 0, p1 = 0, p2 = 0, m00 = 0, m01 = 0, m02 = 0, m11 = 0, m12 = 0, m22 = 0;
    for (int n = lane; n < 100; n += 32) {
        float ww = swt[n];
        float4 v = sY4[wid][n];
        p0 += ww * v.x; p1 += ww * v.y; p2 += ww * v.z;
        m00 += ww * v.x * v.x; m01 += ww * v.x * v.y; m02 += ww * v.x * v.z;
        m11 += ww * v.y * v.y; m12 += ww * v.y * v.z; m22 += ww * v.z * v.z;
    }
#pragma unroll
    for (int off = 16; off > 0; off >>= 1) {
        p0 += __shfl_xor_sync(~0u, p0, off);  p1 += __shfl_xor_sync(~0u, p1, off);
        p2 += __shfl_xor_sync(~0u, p2, off);  m00 += __shfl_xor_sync(~0u, m00, off);
        m01 += __shfl_xor_sync(~0u, m01, off); m02 += __shfl_xor_sync(~0u, m02, off);
        m11 += __shfl_xor_sync(~0u, m11, off); m12 += __shfl_xor_sync(~0u, m12, off);
        m22 += __shfl_xor_sync(~0u, m22, off);
    }
    float iw = sinvw;
    float yw0 = p0 * iw, yw1 = p1 * iw, yw2 = p2 * iw;
    float YY00 = m00 - p0 * p0 * iw, YY01 = m01 - p0 * p1 * iw, YY02 = m02 - p0 * p2 * iw;
    float YY11 = m11 - p1 * p1 * iw, YY12 = m12 - p1 * p2 * iw, YY22 = m22 - p2 * p2 * iw;

    for (int n = lane; n < 100; n += 32) {
        float s = ssw[n];
        float4 v = sY4[wid][n];
        v.x = s * (v.x - yw0); v.y = s * (v.y - yw1); v.z = s * (v.z - yw2);
        sY4[wid][n] = v;
    }
    __syncwarp();

    float* rec = gRec + b * REC;

    if (lane < 30) {
        float a0 = 0, a1 = 0, a2 = 0;
#pragma unroll 4
        for (int n = 0; n < 100; n++) {
            float4 yv = sY4[wid][n];
            float bv = sBb[n * 30 + lane];
            a0 += yv.x * bv; a1 += yv.y * bv; a2 += yv.z * bv;
        }
        int base = 30 * (lane / 10) + (lane % 10);
        sD[wid][base] = a0; sD[wid][base + 10] = a1; sD[wid][base + 20] = a2;
        rec[56 + base] = a0; rec[56 + base + 10] = a1; rec[56 + base + 20] = a2;
    }
    if (lane == 0) {
        sYY[wid][0] = YY00; sYY[wid][1] = YY01; sYY[wid][2] = YY02;
        sYY[wid][3] = YY01; sYY[wid][4] = YY11; sYY[wid][5] = YY12;
        sYY[wid][6] = YY02; sYY[wid][7] = YY12; sYY[wid][8] = YY22;
        rec[146] = yw0; rec[147] = yw1; rec[148] = yw2;
    }
    __syncwarp();

    if (lane < 30) {
        int a = lane / 10, kp = lane % 10;
        float h0 = 0, h1 = 0, h2 = 0;
#pragma unroll
        for (int k = 0; k < 10; k++) {
            float gv = sG[k * 10 + kp];
            h0 += sD[wid][30 * a + k] * gv;
            h1 += sD[wid][30 * a + 10 + k] * gv;
            h2 += sD[wid][30 * a + 20 + k] * gv;
        }
        sT[wid][30 * a + kp] = h0; sT[wid][30 * a + 10 + kp] = h1; sT[wid][30 * a + 20 + kp] = h2;
    }
    __syncwarp();

    for (int u = lane; u < 55; u += 32) {
        int I = 0, uu = u;
        while (uu >= 10 - I) { uu -= 10 - I; I++; }
        int J = I + uu;
        float val;
        if (I == 0) {
            if (J == 0) val = sq00;
            else {
                int c = J - 1;
                float acc2 = 0.f;
#pragma unroll
                for (int k = 0; k < 10; k++) acc2 += sD[wid][c * 10 + k] * sg[k];
                val = -acc2;
            }
        } else {
            int c = I - 1, d = J - 1;
            float acc2 = 0.f;
#pragma unroll
            for (int k = 0; k < 10; k++) acc2 += sT[wid][c * 10 + k] * sD[wid][d * 10 + k];
            val = -2.f * acc2;
            if (c / 3 == d / 3) val += sYY[wid][(c % 3) * 3 + (d % 3)];
        }
        rec[u] = val;
    }
}

// ---------------- phase B: thread per batch ----------------
// Householder tridiagonalization + Sturm bisection + inverse iteration.
__global__ __launch_bounds__(64) void phaseB_kernel(float* __restrict__ out)
{
    int b = blockIdx.x * 64 + threadIdx.x;
    const float* rec = gRec + b * REC;

    float Qp[56];
#pragma unroll
    for (int q4 = 0; q4 < 14; q4++) {
        float4 v = *(const float4*)(rec + q4 * 4);
        Qp[q4 * 4] = v.x; Qp[q4 * 4 + 1] = v.y; Qp[q4 * 4 + 2] = v.z; Qp[q4 * 4 + 3] = v.w;
    }

    float A[10][10];
    {
        int u = 0;
#pragma unroll
        for (int i = 0; i < 10; i++)
#pragma unroll
            for (int j = i; j < 10; j++) {
                A[i][j] = Qp[u]; A[j][i] = Qp[u]; u++;
            }
    }

    float tr = 0.f;
#pragma unroll
    for (int i = 0; i < 10; i++) tr += A[i][i];
    tr = fmaxf(tr, 1e-30f);

    // --- Householder tridiagonalization (v's stored in eliminated columns) ---
    float e[9], beta[8];
#pragma unroll
    for (int k = 0; k < 8; k++) {
        float x0 = A[k + 1][k];
        float snorm = 0.f;
#pragma unroll
        for (int i = k + 2; i < 10; i++) snorm += A[i][k] * A[i][k];
        float nrm = sqrtf(x0 * x0 + snorm);
        float alpha = (x0 >= 0.f) ? -nrm : nrm;
        float v0 = x0 - alpha;
        float vn2 = v0 * v0 + snorm;
        float bt = (vn2 > 1e-30f) ? (2.f / vn2) : 0.f;
        beta[k] = bt;
        e[k] = alpha;
        A[k + 1][k] = v0;   // v lives in A[k+1..9][k]

        float p[10];
#pragma unroll
        for (int i = k + 1; i < 10; i++) {
            float s = 0.f;
#pragma unroll
            for (int j = k + 1; j < 10; j++) s += A[i][j] * A[j][k];
            p[i] = bt * s;
        }
        float vp = 0.f;
#pragma unroll
        for (int i = k + 1; i < 10; i++) vp += p[i] * A[i][k];
        float hb = 0.5f * bt * vp;
#pragma unroll
        for (int i = k + 1; i < 10; i++) p[i] -= hb * A[i][k];
#pragma unroll
        for (int i = k + 1; i < 10; i++)
#pragma unroll
            for (int j = k + 1; j < 10; j++)
                A[i][j] -= A[i][k] * p[j] + p[i] * A[j][k];
    }
    e[8] = A[9][8];
    float d[10];
#pragma unroll
    for (int i = 0; i < 10; i++) d[i] = A[i][i];

    float e2[9];
#pragma unroll
    for (int i = 0; i < 9; i++) e2[i] = e[i] * e[i];

    // --- bracket: [Gershgorin lo, min diag] ---
    float lo = d[0] - fabsf(e[0]);
    float hi = d[0];
#pragma unroll
    for (int i = 1; i < 10; i++) {
        float g = d[i] - fabsf(e[i - 1]) - ((i < 9) ? fabsf(e[i]) : 0.f);
        lo = fminf(lo, g);
        hi = fminf(hi, d[i]);
    }
    float peps = tr * 1e-10f + 1e-30f;

    // --- Sturm bisection (22 iters, branchless) ---
#pragma unroll 1
    for (int it = 0; it < 22; it++) {
        float mid = 0.5f * (lo + hi);
        float q = d[0] - mid;
        int cnt = (q < 0.f);
#pragma unroll
        for (int i = 1; i < 10; i++) {
            float den = (fabsf(q) < peps) ? ((q < 0.f) ? -peps : peps) : q;
            q = d[i] - mid - __fdividef(e2[i - 1], den);
            cnt += (q < 0.f);
        }
        lo = (cnt >= 1) ? lo : mid;
        hi = (cnt >= 1) ? mid : hi;
    }
    float sigma = lo;

    // --- LDL of T - sigma I (clamped) ---
    float cf[10], lf[9];
    float teps = tr * 1e-12f + 1e-32f;
    {
        float q = d[0] - sigma;
        cf[0] = (fabsf(q) < teps) ? ((q < 0.f) ? -teps : teps) : q;
#pragma unroll
        for (int i = 1; i < 10; i++) {
            lf[i - 1] = __fdividef(e[i - 1], cf[i - 1]);
            q = d[i] - sigma - lf[i - 1] * e[i - 1];
            cf[i] = (fabsf(q) < teps) ? ((q < 0.f) ? -teps : teps) : q;
        }
    }

    // --- inverse iteration on tridiagonal (3 iters) ---
    float z[10];
#pragma unroll
    for (int i = 0; i < 10; i++) z[i] = ((i & 1) ? -1.f : 1.f) + 0.21f * (float)i;
#pragma unroll 1
    for (int it = 0; it < 3; it++) {
        float yv[10];
        yv[0] = z[0];
#pragma unroll
        for (int i = 1; i < 10; i++) yv[i] = z[i] - lf[i - 1] * yv[i - 1];
        z[9] = __fdividef(yv[9], cf[9]);
#pragma unroll
        for (int i = 8; i >= 0; i--) z[i] = __fdividef(yv[i] - e[i] * z[i + 1], cf[i]);
        float nn = 0.f;
#pragma unroll
        for (int i = 0; i < 10; i++) nn += z[i] * z[i];
        float inr = rsqrtf(fmaxf(nn, 1e-30f));
#pragma unroll
        for (int i = 0; i < 10; i++) {
            float zv = z[i] * inr;
            z[i] = fminf(fmaxf(zv, -2.f), 2.f);   // NaN/Inf guard (normal |z|<=1)
        }
    }

    // --- back-transform through Householder reflectors ---
#pragma unroll
    for (int k = 7; k >= 0; k--) {
        float t2 = 0.f;
#pragma unroll
        for (int i = k + 1; i < 10; i++) t2 += A[i][k] * z[i];
        t2 *= beta[k];
#pragma unroll
        for (int i = k + 1; i < 10; i++) z[i] -= t2 * A[i][k];
    }

    float inv0 = 1.f / z[0];

    float D[92], yw[3];
#pragma unroll
    for (int q4 = 0; q4 < 23; q4++) {
        float4 v = *(const float4*)(rec + 56 + q4 * 4);
        D[q4 * 4] = v.x; D[q4 * 4 + 1] = v.y; D[q4 * 4 + 2] = v.z; D[q4 * 4 + 3] = v.w;
    }
    yw[0] = D[90]; yw[1] = D[91]; yw[2] = rec[148];

    float Rv[9];
#pragma unroll
    for (int c = 0; c < 9; c++) Rv[c] = z[1 + c] * inv0;

    float uvec[10];
#pragma unroll
    for (int k = 0; k < 10; k++) {
        float s2 = 0.f;
#pragma unroll
        for (int c = 0; c < 9; c++) s2 += Rv[c] * D[c * 10 + k];
        uvec[k] = s2;
    }
    float cv[10];
#pragma unroll
    for (int k = 0; k < 10; k++) {
        float s2 = 0.f;
#pragma unroll
        for (int kp = 0; kp < 10; kp++) s2 += d_G[k * 10 + kp] * uvec[kp];
        cv[k] = 2.f * s2 + d_g[k];
    }
    float inner[3];
#pragma unroll
    for (int a = 0; a < 3; a++) {
        float s2 = 0.f;
#pragma unroll
        for (int k = 0; k < 10; k++) s2 += d_bw[k * 3 + a] * cv[k];
        inner[a] = s2;
    }

#pragma unroll
    for (int r = 0; r < 3; r++)
#pragma unroll
        for (int a = 0; a < 3; a++)
            out[b * 9 + r * 3 + a] = Rv[3 * a + r];
#pragma unroll
    for (int j = 0; j < 3; j++) {
        float tv = yw[j];
#pragma unroll
        for (int a = 0; a < 3; a++) tv -= Rv[3 * a + j] * inner[a];
        out[BSZ * 9 + b * 3 + j] = tv;
    }
#pragma unroll
    for (int k = 0; k < 10; k++)
        out[BSZ * 12 + b * 10 + k] = cv[k];
}

extern "C" void kernel_launch(void* const* d_in, const int* in_sizes, int n_in,
                              void* d_out, int out_size)
{
    const float* y  = (const float*)d_in[0];
    const float* w  = (const float*)d_in[1];
    const float* mk = (const float*)d_in[2];
    float* out = (float*)d_out;
    setup_kernel<<<1, 128>>>(w, mk);
    phaseA_kernel<<<BSZ / WPB, 256>>>(y, w);
    phaseB_kernel<<<BSZ / 64, 64>>>(out);
}

// round 5
// speedup vs baseline: 1.0078x; 1.0078x over previous
#include <cuda_runtime.h>
#include <math.h>

#define BSZ 8192
#define KC 10
#define NC 100
#define LAMBDA 1.0f
#define WPB 8
#define REC 160   // per-batch record: Q[0..54], pad, D[56..145], yw[146..148]

__device__ float d_wsum;
__device__ float d_sw[NC];
__device__ float d_Bb[NC * 30];   // [n][a][k]
__device__ float d_G[KC * KC];
__device__ float d_g[KC];
__device__ float d_bw[KC * 3];    // [k][a]
__device__ float d_q00;
__device__ float gRec[BSZ * REC];

__device__ __forceinline__ void decode_pair(int u, int& k, int& k2)
{
    k = 0;
    while (u >= KC - k) { u -= KC - k; k++; }
    k2 = k + u;
}

// ---------------- setup: fully smem-resident, parallel ----------------
__global__ __launch_bounds__(128) void setup_kernel(const float* __restrict__ w,
                                                    const float* __restrict__ mk)
{
    __shared__ float sMk[3000];
    __shared__ float sW[100];
    __shared__ float sBb[3000];
    __shared__ float sbw[30];
    __shared__ float sPart[112];
    __shared__ float sS[100];
    __shared__ float sM[10][20];
    __shared__ float sF[10];
    __shared__ float sHt[10];
    __shared__ float sInv, s_wsum, s_denom;

    int t = threadIdx.x;
    for (int i = t; i < 3000; i += 128) sMk[i] = mk[i];
    if (t < 100) sW[t] = w[t];
    __syncthreads();

    // wsum
    float a = (t < 100) ? sW[t] : 0.f;
#pragma unroll
    for (int off = 16; off > 0; off >>= 1) a += __shfl_xor_sync(~0u, a, off);
    if ((t & 31) == 0) sPart[96 + (t >> 5)] = a;
    __syncthreads();
    if (t == 0) { s_wsum = sPart[96] + sPart[97] + sPart[98] + sPart[99]; d_wsum = s_wsum; }
    __syncthreads();
    float wsum = s_wsum;
    if (t < 100) d_sw[t] = sqrtf(sW[t]);

    // b_w
    if (t < 30) {
        int k = t / 3, aa = t % 3;
        float s = 0.f;
#pragma unroll 4
        for (int n = 0; n < NC; n++) s += sMk[k * 300 + aa * 100 + n] * sW[n];
        sbw[t] = s / wsum; d_bw[t] = s / wsum;
    }
    __syncthreads();

    // bar_B
    for (int i = t; i < 3000; i += 128) {
        int n = i / 30, rem = i % 30, aa = rem / 10, k = rem % 10;
        float v = sqrtf(sW[n]) * (sMk[k * 300 + aa * 100 + n] - sbw[k * 3 + aa]);
        sBb[i] = v; d_Bb[i] = v;
    }
    __syncthreads();

    // S partials: 2 threads per (k,k2) pair
    if (t < 110) {
        int u = t >> 1, h = t & 1;
        int k, k2; decode_pair(u, k, k2);
        float s = 0.f;
        int i0 = h * 150;
#pragma unroll 3
        for (int idx = i0; idx < i0 + 150; idx++) {
            int n = idx / 3, aa = idx % 3;
            int base = n * 30 + aa * 10;
            s += sBb[base + k] * sBb[base + k2];
        }
        sPart[t] = s;
    }
    __syncthreads();
    if (t < 55) {
        int k, k2; decode_pair(t, k, k2);
        float s = sPart[2 * t] + sPart[2 * t + 1];
        sS[k * 10 + k2] = s; sS[k2 * 10 + k] = s;
    }
    __syncthreads();

    // augmented [H | I]
    if (t < 100) {
        int i = t / 10, j = t % 10;
        sM[i][j] = 2.f * (sS[t] + ((i == j) ? LAMBDA : 0.f));
        sM[i][10 + j] = (i == j) ? 1.f : 0.f;
    }
    __syncthreads();

    // parallel Gauss-Jordan (PD, no pivoting)
    for (int piv = 0; piv < 10; piv++) {
        if (t == 0) sInv = 1.f / sM[piv][piv];
        if (t >= 32 && t < 42) sF[t - 32] = sM[t - 32][piv];
        __syncthreads();
        if (t < 20) sM[piv][t] *= sInv;
        __syncthreads();
        for (int idx = t; idx < 200; idx += 128) {
            int i = idx / 20, j = idx % 20;
            if (i != piv) sM[i][j] -= sF[i] * sM[piv][j];
        }
        __syncthreads();
    }

    if (t < 10) {
        float s = 0.f;
#pragma unroll
        for (int j = 0; j < 10; j++) s += sM[t][10 + j];
        sHt[t] = s;
    }
    __syncthreads();
    if (t == 0) {
        float d = 0.f;
#pragma unroll
        for (int i = 0; i < 10; i++) d += sHt[i];
        s_denom = d;
    }
    __syncthreads();
    float denom = s_denom;
    if (t < 100) d_G[t] = sM[t / 10][10 + (t % 10)] - sHt[t / 10] * sHt[t % 10] / denom;
    if (t < 10) d_g[t] = sHt[t] / denom;
    if (t == 0) {
        float q = 0.f;
        for (int i = 0; i < 10; i++) {
            float gi = sHt[i] / denom;
            float sg = 0.f;
            for (int j = 0; j < 10; j++) sg += sS[i * 10 + j] * sHt[j] / denom;
            q += gi * sg + LAMBDA * gi * gi;
        }
        d_q00 = q;
    }
}

// ---------------- phase A: warp per batch ----------------
__global__ __launch_bounds__(256) void phaseA_kernel(const float* __restrict__ y,
                                                     const float* __restrict__ w)
{
    __shared__ float sBb[3000];
    __shared__ float sG[100];
    __shared__ float sg[12];
    __shared__ float swt[100];
    __shared__ float ssw[100];
    __shared__ float4 sY4[WPB][101];
    __shared__ float sD[WPB][92];
    __shared__ float sT[WPB][92];
    __shared__ float sYY[WPB][12];
    __shared__ float sq00, sinvw;

    int tid = threadIdx.x;
    for (int i = tid; i < 3000; i += 256) sBb[i] = d_Bb[i];
    if (tid < 100) { sG[tid] = d_G[tid]; swt[tid] = w[tid]; ssw[tid] = d_sw[tid]; }
    if (tid < 10) sg[tid] = d_g[tid];
    if (tid == 0) { sq00 = d_q00; sinvw = 1.f / d_wsum; }
    __syncthreads();

    int wid = tid / 32, lane = tid % 32;
    int b = blockIdx.x * WPB + wid;
    const float* yb = y + b * 300;
    float* sYf = (float*)&sY4[wid][0];

    for (int i = lane; i < 300; i += 32) {
        int r = i / 100, n = i % 100;
        sYf[n * 4 + r] = yb[i];
    }
    __syncwarp();

    float p0 = 0, p1 = 0, p2 = 0, m00 = 0, m01 = 0, m02 = 0, m11 = 0, m12 = 0, m22 = 0;
    for (int n = lane; n < 100; n += 32) {
        float ww = swt[n];
        float4 v = sY4[wid][n];
        p0 += ww * v.x; p1 += ww * v.y; p2 += ww * v.z;
        m00 += ww * v.x * v.x; m01 += ww * v.x * v.y; m02 += ww * v.x * v.z;
        m11 += ww * v.y * v.y; m12 += ww * v.y * v.z; m22 += ww * v.z * v.z;
    }
#pragma unroll
    for (int off = 16; off > 0; off >>= 1) {
        p0 += __shfl_xor_sync(~0u, p0, off);  p1 += __shfl_xor_sync(~0u, p1, off);
        p2 += __shfl_xor_sync(~0u, p2, off);  m00 += __shfl_xor_sync(~0u, m00, off);
        m01 += __shfl_xor_sync(~0u, m01, off); m02 += __shfl_xor_sync(~0u, m02, off);
        m11 += __shfl_xor_sync(~0u, m11, off); m12 += __shfl_xor_sync(~0u, m12, off);
        m22 += __shfl_xor_sync(~0u, m22, off);
    }
    float iw = sinvw;
    float yw0 = p0 * iw, yw1 = p1 * iw, yw2 = p2 * iw;
    float YY00 = m00 - p0 * p0 * iw, YY01 = m01 - p0 * p1 * iw, YY02 = m02 - p0 * p2 * iw;
    float YY11 = m11 - p1 * p1 * iw, YY12 = m12 - p1 * p2 * iw, YY22 = m22 - p2 * p2 * iw;

    for (int n = lane; n < 100; n += 32) {
        float s = ssw[n];
        float4 v = sY4[wid][n];
        v.x = s * (v.x - yw0); v.y = s * (v.y - yw1); v.z = s * (v.z - yw2);
        sY4[wid][n] = v;
    }
    __syncwarp();

    float* rec = gRec + b * REC;

    if (lane < 30) {
        float a0 = 0, a1 = 0, a2 = 0;
#pragma unroll 4
        for (int n = 0; n < 100; n++) {
            float4 yv = sY4[wid][n];
            float bv = sBb[n * 30 + lane];
            a0 += yv.x * bv; a1 += yv.y * bv; a2 += yv.z * bv;
        }
        int base = 30 * (lane / 10) + (lane % 10);
        sD[wid][base] = a0; sD[wid][base + 10] = a1; sD[wid][base + 20] = a2;
        rec[56 + base] = a0; rec[56 + base + 10] = a1; rec[56 + base + 20] = a2;
    }
    if (lane == 0) {
        sYY[wid][0] = YY00; sYY[wid][1] = YY01; sYY[wid][2] = YY02;
        sYY[wid][3] = YY01; sYY[wid][4] = YY11; sYY[wid][5] = YY12;
        sYY[wid][6] = YY02; sYY[wid][7] = YY12; sYY[wid][8] = YY22;
        rec[146] = yw0; rec[147] = yw1; rec[148] = yw2;
    }
    __syncwarp();

    if (lane < 30) {
        int a = lane / 10, kp = lane % 10;
        float h0 = 0, h1 = 0, h2 = 0;
#pragma unroll
        for (int k = 0; k < 10; k++) {
            float gv = sG[k * 10 + kp];
            h0 += sD[wid][30 * a + k] * gv;
            h1 += sD[wid][30 * a + 10 + k] * gv;
            h2 += sD[wid][30 * a + 20 + k] * gv;
        }
        sT[wid][30 * a + kp] = h0; sT[wid][30 * a + 10 + kp] = h1; sT[wid][30 * a + 20 + kp] = h2;
    }
    __syncwarp();

    for (int u = lane; u < 55; u += 32) {
        int I = 0, uu = u;
        while (uu >= 10 - I) { uu -= 10 - I; I++; }
        int J = I + uu;
        float val;
        if (I == 0) {
            if (J == 0) val = sq00;
            else {
                int c = J - 1;
                float acc2 = 0.f;
#pragma unroll
                for (int k = 0; k < 10; k++) acc2 += sD[wid][c * 10 + k] * sg[k];
                val = -acc2;
            }
        } else {
            int c = I - 1, d = J - 1;
            float acc2 = 0.f;
#pragma unroll
            for (int k = 0; k < 10; k++) acc2 += sT[wid][c * 10 + k] * sD[wid][d * 10 + k];
            val = -2.f * acc2;
            if (c / 3 == d / 3) val += sYY[wid][(c % 3) * 3 + (d % 3)];
        }
        rec[u] = val;
    }
}

// ---------------- phase B: thread per batch ----------------
__global__ __launch_bounds__(32) void phaseB_kernel(float* __restrict__ out)
{
    int b = blockIdx.x * 32 + threadIdx.x;
    const float* rec = gRec + b * REC;

    float Qp[56];
#pragma unroll
    for (int q4 = 0; q4 < 14; q4++) {
        float4 v = *(const float4*)(rec + q4 * 4);
        Qp[q4 * 4] = v.x; Qp[q4 * 4 + 1] = v.y; Qp[q4 * 4 + 2] = v.z; Qp[q4 * 4 + 3] = v.w;
    }

    float A[10][10];
    {
        int u = 0;
#pragma unroll
        for (int i = 0; i < 10; i++)
#pragma unroll
            for (int j = i; j < 10; j++) {
                A[i][j] = Qp[u]; A[j][i] = Qp[u]; u++;
            }
    }

    float tr = 0.f;
#pragma unroll
    for (int i = 0; i < 10; i++) tr += A[i][i];
    tr = fmaxf(tr, 1e-30f);

    // Householder tridiagonalization
    float e[9], beta[8];
#pragma unroll
    for (int k = 0; k < 8; k++) {
        float x0 = A[k + 1][k];
        float snorm = 0.f;
#pragma unroll
        for (int i = k + 2; i < 10; i++) snorm += A[i][k] * A[i][k];
        float nrm = sqrtf(x0 * x0 + snorm);
        float alpha = (x0 >= 0.f) ? -nrm : nrm;
        float v0 = x0 - alpha;
        float vn2 = v0 * v0 + snorm;
        float bt = (vn2 > 1e-30f) ? (2.f / vn2) : 0.f;
        beta[k] = bt;
        e[k] = alpha;
        A[k + 1][k] = v0;

        float p[10];
#pragma unroll
        for (int i = k + 1; i < 10; i++) {
            float s = 0.f;
#pragma unroll
            for (int j = k + 1; j < 10; j++) s += A[i][j] * A[j][k];
            p[i] = bt * s;
        }
        float vp = 0.f;
#pragma unroll
        for (int i = k + 1; i < 10; i++) vp += p[i] * A[i][k];
        float hb = 0.5f * bt * vp;
#pragma unroll
        for (int i = k + 1; i < 10; i++) p[i] -= hb * A[i][k];
#pragma unroll
        for (int i = k + 1; i < 10; i++)
#pragma unroll
            for (int j = k + 1; j < 10; j++)
                A[i][j] -= A[i][k] * p[j] + p[i] * A[j][k];
    }
    e[8] = A[9][8];
    float d[10];
#pragma unroll
    for (int i = 0; i < 10; i++) d[i] = A[i][i];

    float e2[9];
#pragma unroll
    for (int i = 0; i < 9; i++) e2[i] = e[i] * e[i];

    float lo = d[0] - fabsf(e[0]);
    float hi = d[0];
#pragma unroll
    for (int i = 1; i < 10; i++) {
        float g = d[i] - fabsf(e[i - 1]) - ((i < 9) ? fabsf(e[i]) : 0.f);
        lo = fminf(lo, g);
        hi = fminf(hi, d[i]);
    }
    float peps = tr * 1e-10f + 1e-30f;

#pragma unroll 1
    for (int it = 0; it < 20; it++) {
        float mid = 0.5f * (lo + hi);
        float q = d[0] - mid;
        int cnt = (q < 0.f);
#pragma unroll
        for (int i = 1; i < 10; i++) {
            float den = (fabsf(q) < peps) ? ((q < 0.f) ? -peps : peps) : q;
            q = d[i] - mid - __fdividef(e2[i - 1], den);
            cnt += (q < 0.f);
        }
        lo = (cnt >= 1) ? lo : mid;
        hi = (cnt >= 1) ? mid : hi;
    }
    float sigma = lo;

    float cf[10], lf[9];
    float teps = tr * 1e-12f + 1e-32f;
    {
        float q = d[0] - sigma;
        cf[0] = (fabsf(q) < teps) ? ((q < 0.f) ? -teps : teps) : q;
#pragma unroll
        for (int i = 1; i < 10; i++) {
            lf[i - 1] = __fdividef(e[i - 1], cf[i - 1]);
            q = d[i] - sigma - lf[i - 1] * e[i - 1];
            cf[i] = (fabsf(q) < teps) ? ((q < 0.f) ? -teps : teps) : q;
        }
    }

    float z[10];
#pragma unroll
    for (int i = 0; i < 10; i++) z[i] = ((i & 1) ? -1.f : 1.f) + 0.21f * (float)i;
#pragma unroll 1
    for (int it = 0; it < 3; it++) {
        float yv[10];
        yv[0] = z[0];
#pragma unroll
        for (int i = 1; i < 10; i++) yv[i] = z[i] - lf[i - 1] * yv[i - 1];
        z[9] = __fdividef(yv[9], cf[9]);
#pragma unroll
        for (int i = 8; i >= 0; i--) z[i] = __fdividef(yv[i] - e[i] * z[i + 1], cf[i]);
        float nn = 0.f;
#pragma unroll
        for (int i = 0; i < 10; i++) nn += z[i] * z[i];
        float inr = rsqrtf(fmaxf(nn, 1e-30f));
#pragma unroll
        for (int i = 0; i < 10; i++) {
            float zv = z[i] * inr;
            z[i] = fminf(fmaxf(zv, -2.f), 2.f);
        }
    }

#pragma unroll
    for (int k = 7; k >= 0; k--) {
        float t2 = 0.f;
#pragma unroll
        for (int i = k + 1; i < 10; i++) t2 += A[i][k] * z[i];
        t2 *= beta[k];
#pragma unroll
        for (int i = k + 1; i < 10; i++) z[i] -= t2 * A[i][k];
    }

    float inv0 = 1.f / z[0];

    float D[92], yw[3];
#pragma unroll
    for (int q4 = 0; q4 < 23; q4++) {
        float4 v = *(const float4*)(rec + 56 + q4 * 4);
        D[q4 * 4] = v.x; D[q4 * 4 + 1] = v.y; D[q4 * 4 + 2] = v.z; D[q4 * 4 + 3] = v.w;
    }
    yw[0] = D[90]; yw[1] = D[91]; yw[2] = rec[148];

    float Rv[9];
#pragma unroll
    for (int c = 0; c < 9; c++) Rv[c] = z[1 + c] * inv0;

    float uvec[10];
#pragma unroll
    for (int k = 0; k < 10; k++) {
        float s2 = 0.f;
#pragma unroll
        for (int c = 0; c < 9; c++) s2 += Rv[c] * D[c * 10 + k];
        uvec[k] = s2;
    }
    float cv[10];
#pragma unroll
    for (int k = 0; k < 10; k++) {
        float s2 = 0.f;
#pragma unroll
        for (int kp = 0; kp < 10; kp++) s2 += d_G[k * 10 + kp] * uvec[kp];
        cv[k] = 2.f * s2 + d_g[k];
    }
    float inner[3];
#pragma unroll
    for (int a = 0; a < 3; a++) {
        float s2 = 0.f;
#pragma unroll
        for (int k = 0; k < 10; k++) s2 += d_bw[k * 3 + a] * cv[k];
        inner[a] = s2;
    }

#pragma unroll
    for (int r = 0; r < 3; r++)
#pragma unroll
        for (int a = 0; a < 3; a++)
            out[b * 9 + r * 3 + a] = Rv[3 * a + r];
#pragma unroll
    for (int j = 0; j < 3; j++) {
        float tv = yw[j];
#pragma unroll
        for (int a = 0; a < 3; a++) tv -= Rv[3 * a + j] * inner[a];
        out[BSZ * 9 + b * 3 + j] = tv;
    }
#pragma unroll
    for (int k = 0; k < 10; k++)
        out[BSZ * 12 + b * 10 + k] = cv[k];
}

extern "C" void kernel_launch(void* const* d_in, const int* in_sizes, int n_in,
                              void* d_out, int out_size)
{
    const float* y  = (const float*)d_in[0];
    const float* w  = (const float*)d_in[1];
    const float* mk = (const float*)d_in[2];
    float* out = (float*)d_out;
    setup_kernel<<<1, 128>>>(w, mk);
    phaseA_kernel<<<BSZ / WPB, 256>>>(y, w);
    phaseB_kernel<<<BSZ / 32, 32>>>(out);
}

// round 6
// speedup vs baseline: 1.0705x; 1.0622x over previous
#include <cuda_runtime.h>
#include <math.h>

#define BSZ 8192
#define KC 10
#define NC 100
#define LAMBDA 1.0f
#define WPB 8
#define REC 160   // per-batch record: Q[0..54], pad, D[56..145], yw[146..148]

__device__ float d_G[KC * KC];
__device__ float d_g[KC];
__device__ float d_bw[KC * 3];    // [k][a]
__device__ float gRec[BSZ * REC];

__device__ __forceinline__ void decode_pair(int u, int& k, int& k2)
{
    k = 0;
    while (u >= KC - k) { u -= KC - k; k++; }
    k2 = k + u;
}

// ---------------- phase A: per-block redundant setup + warp-per-batch ----------------
__global__ __launch_bounds__(256) void phaseA_kernel(const float* __restrict__ y,
                                                     const float* __restrict__ w,
                                                     const float* __restrict__ mk)
{
    __shared__ float sW[100], ssw[100];
    __shared__ float sbw[30];
    __shared__ float sPart[224];
    __shared__ float sS[100];
    __shared__ float sM[10][20];
    __shared__ float sF[10];
    __shared__ float sPr[20];
    __shared__ float sHt[10];
    __shared__ float sG[100];
    __shared__ float sg[12];
    __shared__ float sBb[3000];
    __shared__ float sY[WPB][304];
    __shared__ float sD[WPB][92];
    __shared__ float sT[WPB][92];
    __shared__ float sYY[WPB][12];
    __shared__ float sq00, sinvw, sInv, s_denom;

    int t = threadIdx.x;

    // ---- weights, wsum ----
    float wv = (t < 100) ? w[t] : 0.f;
    if (t < 100) { sW[t] = wv; ssw[t] = sqrtf(wv); }
    float a = wv;
#pragma unroll
    for (int off = 16; off > 0; off >>= 1) a += __shfl_xor_sync(~0u, a, off);
    if ((t & 31) == 0) sPart[t >> 5] = a;
    __syncthreads();
    if (t == 0) sinvw = 1.f / (sPart[0] + sPart[1] + sPart[2] + sPart[3]);
    // b_w (un-normalized)
    if (t < 30) {
        int k = t / 3, aa = t % 3;
        const float* m = mk + k * 300 + aa * 100;
        float s = 0.f;
#pragma unroll 4
        for (int n = 0; n < 100; n++) s += m[n] * sW[n];
        sPart[64 + t] = s;
    }
    __syncthreads();
    if (t < 30) sbw[t] = sPart[64 + t] * sinvw;
    __syncthreads();
    // bar_B [n][a][k]
    for (int i = t; i < 3000; i += 256) {
        int n = i / 30, rem = i % 30, aa = rem / 10, k = rem % 10;
        sBb[i] = ssw[n] * (mk[k * 300 + aa * 100 + n] - sbw[k * 3 + aa]);
    }
    __syncthreads();
    // S partials: 220 threads = 55 pairs x 4 chunks of 75 (n,a) entries
    if (t < 220) {
        int u = t >> 2, h = t & 3;
        int k, k2; decode_pair(u, k, k2);
        float s = 0.f;
        for (int idx = h * 75; idx < h * 75 + 75; idx++) {
            int base = (idx / 3) * 30 + (idx % 3) * 10;
            s += sBb[base + k] * sBb[base + k2];
        }
        sPart[t] = s;
    }
    __syncthreads();
    if (t < 55) {
        int k, k2; decode_pair(t, k, k2);
        float s = sPart[4 * t] + sPart[4 * t + 1] + sPart[4 * t + 2] + sPart[4 * t + 3];
        sS[k * 10 + k2] = s; sS[k2 * 10 + k] = s;
    }
    __syncthreads();
    // augmented [H | I]
    if (t < 100) {
        int i = t / 10, j = t % 10;
        sM[i][j] = 2.f * (sS[t] + ((i == j) ? LAMBDA : 0.f));
        sM[i][10 + j] = (i == j) ? 1.f : 0.f;
    }
    __syncthreads();
    // Gauss-Jordan, 2 barriers per pivot, race-free via stashed pivot row
    for (int piv = 0; piv < 10; piv++) {
        if (t < 20) sPr[t] = sM[piv][t];
        if (t >= 32 && t < 42) sF[t - 32] = sM[t - 32][piv];
        if (t == 64) sInv = 1.f / sM[piv][piv];
        __syncthreads();
        if (t < 200) {
            int i = t / 20, j = t % 20;
            float pv = sPr[j] * sInv;
            sM[i][j] = (i == piv) ? pv : sM[i][j] - sF[i] * pv;
        }
        __syncthreads();
    }
    if (t < 10) {
        float s = 0.f;
#pragma unroll
        for (int j = 0; j < 10; j++) s += sM[t][10 + j];
        sHt[t] = s;
    }
    __syncthreads();
    if (t == 0) {
        float dsum = 0.f;
#pragma unroll
        for (int i = 0; i < 10; i++) dsum += sHt[i];
        s_denom = dsum;
    }
    __syncthreads();
    float denom = s_denom;
    if (t < 100) {
        float gv = sM[t / 10][10 + (t % 10)] - sHt[t / 10] * sHt[t % 10] / denom;
        sG[t] = gv;
        if (blockIdx.x == 0) d_G[t] = gv;
    }
    if (t < 10) {
        float gsc = sHt[t] / denom;
        sg[t] = gsc;
        if (blockIdx.x == 0) d_g[t] = gsc;
    }
    if (t < 30 && blockIdx.x == 0) d_bw[t] = sbw[t];
    if (t == 0) {
        float q = 0.f;
        for (int i = 0; i < 10; i++) {
            float gi = sHt[i] / denom, sgs = 0.f;
            for (int j = 0; j < 10; j++) sgs += sS[i * 10 + j] * sHt[j] / denom;
            q += gi * sgs + LAMBDA * gi * gi;
        }
        sq00 = q;
    }
    __syncthreads();

    // ---- per-batch stage: warp per batch ----
    int wid = t / 32, lane = t % 32;
    int b = blockIdx.x * WPB + wid;
    const float* yb = y + b * 300;
    float* Yw = &sY[wid][0];

    for (int i = lane; i < 300; i += 32) {
        int r = i / 100, n = i % 100;
        Yw[n * 3 + r] = yb[i];
    }
    __syncwarp();

    float p0 = 0, p1 = 0, p2 = 0, m00 = 0, m01 = 0, m02 = 0, m11 = 0, m12 = 0, m22 = 0;
    for (int n = lane; n < 100; n += 32) {
        float ww = sW[n];
        float y0 = Yw[n * 3], y1 = Yw[n * 3 + 1], y2 = Yw[n * 3 + 2];
        p0 += ww * y0; p1 += ww * y1; p2 += ww * y2;
        m00 += ww * y0 * y0; m01 += ww * y0 * y1; m02 += ww * y0 * y2;
        m11 += ww * y1 * y1; m12 += ww * y1 * y2; m22 += ww * y2 * y2;
    }
#pragma unroll
    for (int off = 16; off > 0; off >>= 1) {
        p0 += __shfl_xor_sync(~0u, p0, off);  p1 += __shfl_xor_sync(~0u, p1, off);
        p2 += __shfl_xor_sync(~0u, p2, off);  m00 += __shfl_xor_sync(~0u, m00, off);
        m01 += __shfl_xor_sync(~0u, m01, off); m02 += __shfl_xor_sync(~0u, m02, off);
        m11 += __shfl_xor_sync(~0u, m11, off); m12 += __shfl_xor_sync(~0u, m12, off);
        m22 += __shfl_xor_sync(~0u, m22, off);
    }
    float iw = sinvw;
    float yw0 = p0 * iw, yw1 = p1 * iw, yw2 = p2 * iw;
    float YY00 = m00 - p0 * p0 * iw, YY01 = m01 - p0 * p1 * iw, YY02 = m02 - p0 * p2 * iw;
    float YY11 = m11 - p1 * p1 * iw, YY12 = m12 - p1 * p2 * iw, YY22 = m22 - p2 * p2 * iw;

    for (int n = lane; n < 100; n += 32) {
        float s = ssw[n];
        Yw[n * 3]     = s * (Yw[n * 3]     - yw0);
        Yw[n * 3 + 1] = s * (Yw[n * 3 + 1] - yw1);
        Yw[n * 3 + 2] = s * (Yw[n * 3 + 2] - yw2);
    }
    __syncwarp();

    float* rec = gRec + b * REC;

    if (lane < 30) {
        float a0 = 0, a1 = 0, a2 = 0;
#pragma unroll 4
        for (int n = 0; n < 100; n++) {
            float y0 = Yw[n * 3], y1 = Yw[n * 3 + 1], y2 = Yw[n * 3 + 2];
            float bv = sBb[n * 30 + lane];
            a0 += y0 * bv; a1 += y1 * bv; a2 += y2 * bv;
        }
        int base = 30 * (lane / 10) + (lane % 10);
        sD[wid][base] = a0; sD[wid][base + 10] = a1; sD[wid][base + 20] = a2;
        rec[56 + base] = a0; rec[56 + base + 10] = a1; rec[56 + base + 20] = a2;
    }
    if (lane == 0) {
        sYY[wid][0] = YY00; sYY[wid][1] = YY01; sYY[wid][2] = YY02;
        sYY[wid][3] = YY01; sYY[wid][4] = YY11; sYY[wid][5] = YY12;
        sYY[wid][6] = YY02; sYY[wid][7] = YY12; sYY[wid][8] = YY22;
        rec[146] = yw0; rec[147] = yw1; rec[148] = yw2;
    }
    __syncwarp();

    if (lane < 30) {
        int aa = lane / 10, kp = lane % 10;
        float h0 = 0, h1 = 0, h2 = 0;
#pragma unroll
        for (int k = 0; k < 10; k++) {
            float gv = sG[k * 10 + kp];
            h0 += sD[wid][30 * aa + k] * gv;
            h1 += sD[wid][30 * aa + 10 + k] * gv;
            h2 += sD[wid][30 * aa + 20 + k] * gv;
        }
        sT[wid][30 * aa + kp] = h0; sT[wid][30 * aa + 10 + kp] = h1; sT[wid][30 * aa + 20 + kp] = h2;
    }
    __syncwarp();

    for (int u = lane; u < 55; u += 32) {
        int I = 0, uu = u;
        while (uu >= 10 - I) { uu -= 10 - I; I++; }
        int J = I + uu;
        float val;
        if (I == 0) {
            if (J == 0) val = sq00;
            else {
                int c = J - 1;
                float acc2 = 0.f;
#pragma unroll
                for (int k = 0; k < 10; k++) acc2 += sD[wid][c * 10 + k] * sg[k];
                val = -acc2;
            }
        } else {
            int c = I - 1, d = J - 1;
            float acc2 = 0.f;
#pragma unroll
            for (int k = 0; k < 10; k++) acc2 += sT[wid][c * 10 + k] * sD[wid][d * 10 + k];
            val = -2.f * acc2;
            if (c / 3 == d / 3) val += sYY[wid][(c % 3) * 3 + (d % 3)];
        }
        rec[u] = val;
    }
}

// ---------------- phase B: thread per batch ----------------
__global__ __launch_bounds__(32) void phaseB_kernel(float* __restrict__ out)
{
    int b = blockIdx.x * 32 + threadIdx.x;
    const float* rec = gRec + b * REC;

    float Qp[56];
#pragma unroll
    for (int q4 = 0; q4 < 14; q4++) {
        float4 v = *(const float4*)(rec + q4 * 4);
        Qp[q4 * 4] = v.x; Qp[q4 * 4 + 1] = v.y; Qp[q4 * 4 + 2] = v.z; Qp[q4 * 4 + 3] = v.w;
    }

    float A[10][10];
    {
        int u = 0;
#pragma unroll
        for (int i = 0; i < 10; i++)
#pragma unroll
            for (int j = i; j < 10; j++) {
                A[i][j] = Qp[u]; A[j][i] = Qp[u]; u++;
            }
    }

    float tr = 0.f;
#pragma unroll
    for (int i = 0; i < 10; i++) tr += A[i][i];
    tr = fmaxf(tr, 1e-30f);

    float e[9], beta[8];
#pragma unroll
    for (int k = 0; k < 8; k++) {
        float x0 = A[k + 1][k];
        float snorm = 0.f;
#pragma unroll
        for (int i = k + 2; i < 10; i++) snorm += A[i][k] * A[i][k];
        float nrm = sqrtf(x0 * x0 + snorm);
        float alpha = (x0 >= 0.f) ? -nrm : nrm;
        float v0 = x0 - alpha;
        float vn2 = v0 * v0 + snorm;
        float bt = (vn2 > 1e-30f) ? (2.f / vn2) : 0.f;
        beta[k] = bt;
        e[k] = alpha;
        A[k + 1][k] = v0;

        float p[10];
#pragma unroll
        for (int i = k + 1; i < 10; i++) {
            float s = 0.f;
#pragma unroll
            for (int j = k + 1; j < 10; j++) s += A[i][j] * A[j][k];
            p[i] = bt * s;
        }
        float vp = 0.f;
#pragma unroll
        for (int i = k + 1; i < 10; i++) vp += p[i] * A[i][k];
        float hb = 0.5f * bt * vp;
#pragma unroll
        for (int i = k + 1; i < 10; i++) p[i] -= hb * A[i][k];
#pragma unroll
        for (int i = k + 1; i < 10; i++)
#pragma unroll
            for (int j = k + 1; j < 10; j++)
                A[i][j] -= A[i][k] * p[j] + p[i] * A[j][k];
    }
    e[8] = A[9][8];
    float d[10];
#pragma unroll
    for (int i = 0; i < 10; i++) d[i] = A[i][i];

    float e2[9];
#pragma unroll
    for (int i = 0; i < 9; i++) e2[i] = e[i] * e[i];

    float lo = d[0] - fabsf(e[0]);
    float hi = d[0];
#pragma unroll
    for (int i = 1; i < 10; i++) {
        float g = d[i] - fabsf(e[i - 1]) - ((i < 9) ? fabsf(e[i]) : 0.f);
        lo = fminf(lo, g);
        hi = fminf(hi, d[i]);
    }
    float peps = tr * 1e-10f + 1e-30f;

#pragma unroll 1
    for (int it = 0; it < 20; it++) {
        float mid = 0.5f * (lo + hi);
        float q = d[0] - mid;
        int cnt = (q < 0.f);
#pragma unroll
        for (int i = 1; i < 10; i++) {
            float den = (fabsf(q) < peps) ? ((q < 0.f) ? -peps : peps) : q;
            q = d[i] - mid - __fdividef(e2[i - 1], den);
            cnt += (q < 0.f);
        }
        lo = (cnt >= 1) ? lo : mid;
        hi = (cnt >= 1) ? mid : hi;
    }
    float sigma = lo;

    float cf[10], lf[9];
    float teps = tr * 1e-12f + 1e-32f;
    {
        float q = d[0] - sigma;
        cf[0] = (fabsf(q) < teps) ? ((q < 0.f) ? -teps : teps) : q;
#pragma unroll
        for (int i = 1; i < 10; i++) {
            lf[i - 1] = __fdividef(e[i - 1], cf[i - 1]);
            q = d[i] - sigma - lf[i - 1] * e[i - 1];
            cf[i] = (fabsf(q) < teps) ? ((q < 0.f) ? -teps : teps) : q;
        }
    }

    float z[10];
#pragma unroll
    for (int i = 0; i < 10; i++) z[i] = ((i & 1) ? -1.f : 1.f) + 0.21f * (float)i;
#pragma unroll 1
    for (int it = 0; it < 3; it++) {
        float yv[10];
        yv[0] = z[0];
#pragma unroll
        for (int i = 1; i < 10; i++) yv[i] = z[i] - lf[i - 1] * yv[i - 1];
        z[9] = __fdividef(yv[9], cf[9]);
#pragma unroll
        for (int i = 8; i >= 0; i--) z[i] = __fdividef(yv[i] - e[i] * z[i + 1], cf[i]);
        float nn = 0.f;
#pragma unroll
        for (int i = 0; i < 10; i++) nn += z[i] * z[i];
        float inr = rsqrtf(fmaxf(nn, 1e-30f));
#pragma unroll
        for (int i = 0; i < 10; i++) {
            float zv = z[i] * inr;
            z[i] = fminf(fmaxf(zv, -2.f), 2.f);
        }
    }

#pragma unroll
    for (int k = 7; k >= 0; k--) {
        float t2 = 0.f;
#pragma unroll
        for (int i = k + 1; i < 10; i++) t2 += A[i][k] * z[i];
        t2 *= beta[k];
#pragma unroll
        for (int i = k + 1; i < 10; i++) z[i] -= t2 * A[i][k];
    }

    float inv0 = 1.f / z[0];

    float D[92], yw[3];
#pragma unroll
    for (int q4 = 0; q4 < 23; q4++) {
        float4 v = *(const float4*)(rec + 56 + q4 * 4);
        D[q4 * 4] = v.x; D[q4 * 4 + 1] = v.y; D[q4 * 4 + 2] = v.z; D[q4 * 4 + 3] = v.w;
    }
    yw[0] = D[90]; yw[1] = D[91]; yw[2] = rec[148];

    float Rv[9];
#pragma unroll
    for (int c = 0; c < 9; c++) Rv[c] = z[1 + c] * inv0;

    float uvec[10];
#pragma unroll
    for (int k = 0; k < 10; k++) {
        float s2 = 0.f;
#pragma unroll
        for (int c = 0; c < 9; c++) s2 += Rv[c] * D[c * 10 + k];
        uvec[k] = s2;
    }
    float cv[10];
#pragma unroll
    for (int k = 0; k < 10; k++) {
        float s2 = 0.f;
#pragma unroll
        for (int kp = 0; kp < 10; kp++) s2 += d_G[k * 10 + kp] * uvec[kp];
        cv[k] = 2.f * s2 + d_g[k];
    }
    float inner[3];
#pragma unroll
    for (int a = 0; a < 3; a++) {
        float s2 = 0.f;
#pragma unroll
        for (int k = 0; k < 10; k++) s2 += d_bw[k * 3 + a] * cv[k];
        inner[a] = s2;
    }

#pragma unroll
    for (int r = 0; r < 3; r++)
#pragma unroll
        for (int a = 0; a < 3; a++)
            out[b * 9 + r * 3 + a] = Rv[3 * a + r];
#pragma unroll
    for (int j = 0; j < 3; j++) {
        float tv = yw[j];
#pragma unroll
        for (int a = 0; a < 3; a++) tv -= Rv[3 * a + j] * inner[a];
        out[BSZ * 9 + b * 3 + j] = tv;
    }
#pragma unroll
    for (int k = 0; k < 10; k++)
        out[BSZ * 12 + b * 10 + k] = cv[k];
}

extern "C" void kernel_launch(void* const* d_in, const int* in_sizes, int n_in,
                              void* d_out, int out_size)
{
    const float* y  = (const float*)d_in[0];
    const float* w  = (const float*)d_in[1];
    const float* mk = (const float*)d_in[2];
    float* out = (float*)d_out;
    phaseA_kernel<<<BSZ / WPB, 256>>>(y, w, mk);
    phaseB_kernel<<<BSZ / 32, 32>>>(out);
}